// round 1
// baseline (speedup 1.0000x reference)
#include <cuda_runtime.h>
#include <cstdint>
#include <cmath>

#define CDIM 512
#define NDIM 512
#define BDIM 64
#define TT 4
#define BP 16           // BDIM / TT
#define HH 8
#define GDIM 64
#define EPSF 1e-5f
#define CN (CDIM*NDIM)  // 262144

// ---------------------------------------------------------------------------
// Scratch (device globals: allocation-free per harness rules)
// ---------------------------------------------------------------------------
__device__ float         g_pre [3ull*BDIM*CN];   // qkv pre-activations
__device__ unsigned char g_spk [3ull*BDIM*CN];   // qkv spikes
__device__ float         g_attn[(unsigned long long)BDIM*CN]; // attn out pre-LIF
__device__ unsigned char g_spk4[(unsigned long long)BDIM*CN]; // final spikes

// ---------------------------------------------------------------------------
// helpers
// ---------------------------------------------------------------------------
__device__ __forceinline__ float4 load4(const float* p) { return *(const float4*)p; }
__device__ __forceinline__ float4 load4(const unsigned char* p) {
    uchar4 u = *(const uchar4*)p;
    return make_float4((float)u.x, (float)u.y, (float)u.z, (float)u.w);
}

// ---------------------------------------------------------------------------
// Fused 1x1-conv (GEMM) + BatchNorm epilogue.
// Y[b][o][n] = inv[o] * sum_c A[o][c] * X[b][c][n] + bias[o]
// A: [512][512] row-major, X: [BDIM][512][512], Y: [BDIM][512][512]
// Tiling: CTA 128x128, K-tile 16, 256 threads, 8x8 per thread, double buffer.
// ---------------------------------------------------------------------------
template<typename TIn>
__global__ void __launch_bounds__(256, 2)
gemm_bn_kernel(const float* __restrict__ A,
               const TIn*  __restrict__ Xbase,
               float*      __restrict__ Ybase,
               const float* __restrict__ bn_g,
               const float* __restrict__ bn_b,
               const float* __restrict__ bn_m,
               const float* __restrict__ bn_v)
{
    const int b = blockIdx.z;
    const TIn*  X = Xbase + (size_t)b * CN;
    float*      Y = Ybase + (size_t)b * CN;

    __shared__ float As[2][16][128];
    __shared__ float Xs[2][16][128];

    const int tid   = threadIdx.x;
    const int mBase = blockIdx.y * 128;
    const int nBase = blockIdx.x * 128;
    const int row0  = (tid >> 4) * 8;   // 0..120
    const int col0  = (tid & 15) * 8;   // 0..120

    float acc[8][8];
    #pragma unroll
    for (int i = 0; i < 8; ++i)
        #pragma unroll
        for (int j = 0; j < 8; ++j) acc[i][j] = 0.f;

    // prologue: load k-tile 0
    #pragma unroll
    for (int i = 0; i < 2; ++i) {
        int f4 = tid + i * 256;
        int r  = f4 >> 2, kc = (f4 & 3) * 4;
        float4 va = load4(A + (size_t)(mBase + r) * CDIM + kc);
        As[0][kc+0][r] = va.x; As[0][kc+1][r] = va.y;
        As[0][kc+2][r] = va.z; As[0][kc+3][r] = va.w;
        int kr = f4 >> 5, nc = (f4 & 31) * 4;
        float4 vx = load4(X + (size_t)kr * NDIM + nBase + nc);
        *(float4*)&Xs[0][kr][nc] = vx;
    }
    __syncthreads();

    int buf = 0;
    for (int kt = 0; kt < 32; ++kt) {
        float4 pa[2], px[2];
        if (kt < 31) {
            const int k0 = (kt + 1) * 16;
            #pragma unroll
            for (int i = 0; i < 2; ++i) {
                int f4 = tid + i * 256;
                int r  = f4 >> 2, kc = (f4 & 3) * 4;
                pa[i] = load4(A + (size_t)(mBase + r) * CDIM + k0 + kc);
                int kr = f4 >> 5, nc = (f4 & 31) * 4;
                px[i] = load4(X + (size_t)(k0 + kr) * NDIM + nBase + nc);
            }
        }
        #pragma unroll
        for (int kk = 0; kk < 16; ++kk) {
            float a[8], bx[8];
            *(float4*)&a[0]  = *(float4*)&As[buf][kk][row0];
            *(float4*)&a[4]  = *(float4*)&As[buf][kk][row0 + 4];
            *(float4*)&bx[0] = *(float4*)&Xs[buf][kk][col0];
            *(float4*)&bx[4] = *(float4*)&Xs[buf][kk][col0 + 4];
            #pragma unroll
            for (int i = 0; i < 8; ++i)
                #pragma unroll
                for (int j = 0; j < 8; ++j)
                    acc[i][j] += a[i] * bx[j];
        }
        if (kt < 31) {
            #pragma unroll
            for (int i = 0; i < 2; ++i) {
                int f4 = tid + i * 256;
                int r  = f4 >> 2, kc = (f4 & 3) * 4;
                As[buf^1][kc+0][r] = pa[i].x; As[buf^1][kc+1][r] = pa[i].y;
                As[buf^1][kc+2][r] = pa[i].z; As[buf^1][kc+3][r] = pa[i].w;
                int kr = f4 >> 5, nc = (f4 & 31) * 4;
                *(float4*)&Xs[buf^1][kr][nc] = px[i];
            }
        }
        __syncthreads();
        buf ^= 1;
    }

    // epilogue: BN (eval mode): y*inv + (beta - mean*inv)
    #pragma unroll
    for (int i = 0; i < 8; ++i) {
        int o = mBase + row0 + i;
        float inv  = bn_g[o] / sqrtf(bn_v[o] + EPSF);
        float bias = bn_b[o] - bn_m[o] * inv;
        float4 r0, r1;
        r0.x = acc[i][0]*inv + bias; r0.y = acc[i][1]*inv + bias;
        r0.z = acc[i][2]*inv + bias; r0.w = acc[i][3]*inv + bias;
        r1.x = acc[i][4]*inv + bias; r1.y = acc[i][5]*inv + bias;
        r1.z = acc[i][6]*inv + bias; r1.w = acc[i][7]*inv + bias;
        *(float4*)(Y + (size_t)o * NDIM + nBase + col0)     = r0;
        *(float4*)(Y + (size_t)o * NDIM + nBase + col0 + 4) = r1;
    }
}

// ---------------------------------------------------------------------------
// LIF scan over T timesteps. Batch index b = t*BP + b'.
// mem = mem*0.5 + x ; spike = mem > 1 ; mem = spike ? 0 : mem
// ---------------------------------------------------------------------------
__global__ void lif_kernel(const float* __restrict__ pre,
                           unsigned char* __restrict__ spk,
                           int ntensors)
{
    size_t idx   = (size_t)blockIdx.x * blockDim.x + threadIdx.x;
    size_t total = (size_t)ntensors * BP * (CN / 4);
    if (idx >= total) return;
    int j4    = (int)(idx % (CN / 4));
    int rest  = (int)(idx / (CN / 4));
    int bp    = rest % BP;
    int which = rest / BP;

    const float* p = pre + (size_t)which * BDIM * CN;
    unsigned char* s = spk + (size_t)which * BDIM * CN;

    float4 mem = make_float4(0.f, 0.f, 0.f, 0.f);
    #pragma unroll
    for (int t = 0; t < TT; ++t) {
        size_t off = (size_t)(t * BP + bp) * CN + (size_t)j4 * 4;
        float4 xi = *(const float4*)(p + off);
        mem.x = mem.x * 0.5f + xi.x;
        mem.y = mem.y * 0.5f + xi.y;
        mem.z = mem.z * 0.5f + xi.z;
        mem.w = mem.w * 0.5f + xi.w;
        uchar4 sp;
        sp.x = mem.x > 1.0f; if (sp.x) mem.x = 0.f;
        sp.y = mem.y > 1.0f; if (sp.y) mem.y = 0.f;
        sp.z = mem.z > 1.0f; if (sp.z) mem.z = 0.f;
        sp.w = mem.w > 1.0f; if (sp.w) mem.w = 0.f;
        *(uchar4*)(s + off) = sp;
    }
}

// ---------------------------------------------------------------------------
// Spiking attention via linear-attention reordering:
//   M[e][d]  = sum_m k[e][m] * v[d][m]          (popcount on bitpacked spikes)
//   out[d][n] = SCALE * sum_e q[e][n] * M[e][d]
// One CTA per (b, h). Exact integer arithmetic -> bit-identical to reference.
// ---------------------------------------------------------------------------
__global__ void __launch_bounds__(256)
attn_kernel(const unsigned char* __restrict__ spk,
            float* __restrict__ attn)
{
    const int bh = blockIdx.x;           // 0..511
    const int b  = bh / HH;
    const int h  = bh % HH;
    const size_t head_off = ((size_t)b * CDIM + (size_t)h * GDIM) * NDIM;
    const unsigned char* qS = spk + 0ull * BDIM * CN + head_off;
    const unsigned char* kS = spk + 1ull * BDIM * CN + head_off;
    const unsigned char* vS = spk + 2ull * BDIM * CN + head_off;

    __shared__ unsigned int kb[64][16];
    __shared__ unsigned int vb[64][16];
    __shared__ float        Ms[64][64];
    __shared__ unsigned char qs[64][128];

    const int tid  = threadIdx.x;
    const int lane = tid & 31;
    const int warp = tid >> 5;           // 8 warps

    // bitpack k and v rows via ballot
    #pragma unroll
    for (int r = 0; r < 8; ++r) {
        int e = warp * 8 + r;
        #pragma unroll
        for (int w = 0; w < 16; ++w) {
            unsigned int bkk = __ballot_sync(0xffffffffu, kS[(size_t)e * NDIM + w * 32 + lane] != 0);
            unsigned int bvv = __ballot_sync(0xffffffffu, vS[(size_t)e * NDIM + w * 32 + lane] != 0);
            if (lane == 0) { kb[e][w] = bkk; vb[e][w] = bvv; }
        }
    }
    __syncthreads();

    // M[e][d] * SCALE via popcount; 16 entries per thread
    {
        int e  = tid >> 2;
        int d0 = (tid & 3) * 16;
        unsigned int kr[16];
        #pragma unroll
        for (int w = 0; w < 16; ++w) kr[w] = kb[e][w];
        #pragma unroll
        for (int dd = 0; dd < 16; ++dd) {
            int d = d0 + dd;
            int s = 0;
            #pragma unroll
            for (int w = 0; w < 16; ++w) s += __popc(kr[w] & vb[d][w]);
            Ms[e][d] = (float)s * 0.125f;
        }
    }
    __syncthreads();

    // out[d][n] = sum_e q[e][n] * Ms[e][d]
    const int nLocal = tid & 127;         // n within chunk
    const int d0     = (tid >> 7) * 32;   // 0 or 32
    float* outp = attn + head_off;

    for (int ch = 0; ch < 4; ++ch) {
        const int nb = ch * 128;
        // stage q chunk (64 rows x 128 cols, u8)
        for (int w = tid; w < 2048; w += 256) {
            int e = w >> 5, nl4 = (w & 31) << 2;
            *(unsigned int*)&qs[e][nl4] =
                *(const unsigned int*)(qS + (size_t)e * NDIM + nb + nl4);
        }
        __syncthreads();

        float acc[32];
        #pragma unroll
        for (int j = 0; j < 32; ++j) acc[j] = 0.f;

        #pragma unroll 4
        for (int e = 0; e < 64; ++e) {
            float qv = (float)qs[e][nLocal];
            #pragma unroll
            for (int j = 0; j < 32; ++j)
                acc[j] += qv * Ms[e][d0 + j];
        }
        #pragma unroll
        for (int j = 0; j < 32; ++j)
            outp[(size_t)(d0 + j) * NDIM + nb + nLocal] = acc[j];
        __syncthreads();
    }
}

// ---------------------------------------------------------------------------
// launch
// ---------------------------------------------------------------------------
extern "C" void kernel_launch(void* const* d_in, const int* in_sizes, int n_in,
                              void* d_out, int out_size)
{
    (void)in_sizes; (void)n_in; (void)out_size;
    const float* x  = (const float*)d_in[0];
    const float* wq = (const float*)d_in[1];
    const float* wk = (const float*)d_in[2];
    const float* wv = (const float*)d_in[3];
    const float* wp = (const float*)d_in[4];
    const float* bg = (const float*)d_in[5];
    const float* bb = (const float*)d_in[6];
    const float* bm = (const float*)d_in[7];
    const float* bv = (const float*)d_in[8];
    float* out = (float*)d_out;

    float* pre;  unsigned char* spk;
    float* attn; unsigned char* spk4;
    cudaGetSymbolAddress((void**)&pre,  g_pre);
    cudaGetSymbolAddress((void**)&spk,  g_spk);
    cudaGetSymbolAddress((void**)&attn, g_attn);
    cudaGetSymbolAddress((void**)&spk4, g_spk4);

    dim3 blk(256);
    dim3 grd(NDIM / 128, CDIM / 128, BDIM);

    const float* W[3] = { wq, wk, wv };
    for (int w = 0; w < 3; ++w) {
        gemm_bn_kernel<float><<<grd, blk>>>(
            W[w], x, pre + (size_t)w * BDIM * CN,
            bg + w * CDIM, bb + w * CDIM, bm + w * CDIM, bv + w * CDIM);
    }

    {   // LIF over q/k/v pre-activations
        size_t total = 3ull * BP * (CN / 4);
        int blocks = (int)((total + 255) / 256);
        lif_kernel<<<blocks, 256>>>(pre, spk, 3);
    }

    attn_kernel<<<BDIM * HH, 256>>>(spk, attn);

    {   // LIF over attention output
        size_t total = 1ull * BP * (CN / 4);
        int blocks = (int)((total + 255) / 256);
        lif_kernel<<<blocks, 256>>>(attn, spk4, 1);
    }

    gemm_bn_kernel<unsigned char><<<grd, blk>>>(
        wp, spk4, out,
        bg + 3 * CDIM, bb + 3 * CDIM, bm + 3 * CDIM, bv + 3 * CDIM);
}

// round 2
// speedup vs baseline: 1.0245x; 1.0245x over previous
#include <cuda_runtime.h>
#include <cstdint>
#include <cmath>

#define CDIM 512
#define NDIM 512
#define BDIM 64
#define TT 4
#define BP 16           // BDIM / TT
#define HH 8
#define GDIM 64
#define EPSF 1e-5f
#define CN (CDIM*NDIM)  // 262144

// ---------------------------------------------------------------------------
// Scratch (device globals: allocation-free per harness rules)
// ---------------------------------------------------------------------------
__device__ float         g_pre [3ull*BDIM*CN];   // qkv pre-activations
__device__ unsigned char g_spk [3ull*BDIM*CN];   // qkv spikes
__device__ float         g_attn[(unsigned long long)BDIM*CN]; // attn out pre-LIF
__device__ unsigned char g_spk4[(unsigned long long)BDIM*CN]; // final spikes

// ---------------------------------------------------------------------------
// helpers
// ---------------------------------------------------------------------------
__device__ __forceinline__ float4 load4(const float* p) { return *(const float4*)p; }
__device__ __forceinline__ float4 load4(const unsigned char* p) {
    uchar4 u = *(const uchar4*)p;
    return make_float4((float)u.x, (float)u.y, (float)u.z, (float)u.w);
}

// ---------------------------------------------------------------------------
// Fused 1x1-conv (GEMM) + BatchNorm epilogue.
// Y[b][o][n] = inv[o] * sum_c A[o][c] * X[b][c][n] + bias[o]
// A: [512][512] row-major, X: [BDIM][512][512], Y: [BDIM][512][512]
// Tiling: CTA 128x128, K-tile 16, 256 threads, 8x8 per thread, double buffer.
// ---------------------------------------------------------------------------
template<typename TIn>
__global__ void __launch_bounds__(256, 2)
gemm_bn_kernel(const float* __restrict__ A,
               const TIn*  __restrict__ Xbase,
               float*      __restrict__ Ybase,
               const float* __restrict__ bn_g,
               const float* __restrict__ bn_b,
               const float* __restrict__ bn_m,
               const float* __restrict__ bn_v)
{
    const int b = blockIdx.z;
    const TIn*  X = Xbase + (size_t)b * CN;
    float*      Y = Ybase + (size_t)b * CN;

    __shared__ float As[2][16][128];
    __shared__ float Xs[2][16][128];

    const int tid   = threadIdx.x;
    const int mBase = blockIdx.y * 128;
    const int nBase = blockIdx.x * 128;
    const int row0  = (tid >> 4) * 8;   // 0..120
    const int col0  = (tid & 15) * 8;   // 0..120

    float acc[8][8];
    #pragma unroll
    for (int i = 0; i < 8; ++i)
        #pragma unroll
        for (int j = 0; j < 8; ++j) acc[i][j] = 0.f;

    // prologue: load k-tile 0
    #pragma unroll
    for (int i = 0; i < 2; ++i) {
        int f4 = tid + i * 256;
        int r  = f4 >> 2, kc = (f4 & 3) * 4;
        float4 va = load4(A + (size_t)(mBase + r) * CDIM + kc);
        As[0][kc+0][r] = va.x; As[0][kc+1][r] = va.y;
        As[0][kc+2][r] = va.z; As[0][kc+3][r] = va.w;
        int kr = f4 >> 5, nc = (f4 & 31) * 4;
        float4 vx = load4(X + (size_t)kr * NDIM + nBase + nc);
        *(float4*)&Xs[0][kr][nc] = vx;
    }
    __syncthreads();

    int buf = 0;
    for (int kt = 0; kt < 32; ++kt) {
        float4 pa[2], px[2];
        if (kt < 31) {
            const int k0 = (kt + 1) * 16;
            #pragma unroll
            for (int i = 0; i < 2; ++i) {
                int f4 = tid + i * 256;
                int r  = f4 >> 2, kc = (f4 & 3) * 4;
                pa[i] = load4(A + (size_t)(mBase + r) * CDIM + k0 + kc);
                int kr = f4 >> 5, nc = (f4 & 31) * 4;
                px[i] = load4(X + (size_t)(k0 + kr) * NDIM + nBase + nc);
            }
        }
        #pragma unroll
        for (int kk = 0; kk < 16; ++kk) {
            float a[8], bx[8];
            *(float4*)&a[0]  = *(float4*)&As[buf][kk][row0];
            *(float4*)&a[4]  = *(float4*)&As[buf][kk][row0 + 4];
            *(float4*)&bx[0] = *(float4*)&Xs[buf][kk][col0];
            *(float4*)&bx[4] = *(float4*)&Xs[buf][kk][col0 + 4];
            #pragma unroll
            for (int i = 0; i < 8; ++i)
                #pragma unroll
                for (int j = 0; j < 8; ++j)
                    acc[i][j] += a[i] * bx[j];
        }
        if (kt < 31) {
            #pragma unroll
            for (int i = 0; i < 2; ++i) {
                int f4 = tid + i * 256;
                int r  = f4 >> 2, kc = (f4 & 3) * 4;
                As[buf^1][kc+0][r] = pa[i].x; As[buf^1][kc+1][r] = pa[i].y;
                As[buf^1][kc+2][r] = pa[i].z; As[buf^1][kc+3][r] = pa[i].w;
                int kr = f4 >> 5, nc = (f4 & 31) * 4;
                *(float4*)&Xs[buf^1][kr][nc] = px[i];
            }
        }
        __syncthreads();
        buf ^= 1;
    }

    // epilogue: BN (eval mode): y*inv + (beta - mean*inv)
    #pragma unroll
    for (int i = 0; i < 8; ++i) {
        int o = mBase + row0 + i;
        float inv  = bn_g[o] / sqrtf(bn_v[o] + EPSF);
        float bias = bn_b[o] - bn_m[o] * inv;
        float4 r0, r1;
        r0.x = acc[i][0]*inv + bias; r0.y = acc[i][1]*inv + bias;
        r0.z = acc[i][2]*inv + bias; r0.w = acc[i][3]*inv + bias;
        r1.x = acc[i][4]*inv + bias; r1.y = acc[i][5]*inv + bias;
        r1.z = acc[i][6]*inv + bias; r1.w = acc[i][7]*inv + bias;
        *(float4*)(Y + (size_t)o * NDIM + nBase + col0)     = r0;
        *(float4*)(Y + (size_t)o * NDIM + nBase + col0 + 4) = r1;
    }
}

// ---------------------------------------------------------------------------
// LIF scan over T timesteps. Batch index b = t*BP + b'.
// mem = mem*0.5 + x ; spike = mem > 1 ; mem = spike ? 0 : mem
// ---------------------------------------------------------------------------
__global__ void lif_kernel(const float* __restrict__ pre,
                           unsigned char* __restrict__ spk,
                           int ntensors)
{
    size_t idx   = (size_t)blockIdx.x * blockDim.x + threadIdx.x;
    size_t total = (size_t)ntensors * BP * (CN / 4);
    if (idx >= total) return;
    int j4    = (int)(idx % (CN / 4));
    int rest  = (int)(idx / (CN / 4));
    int bp    = rest % BP;
    int which = rest / BP;

    const float* p = pre + (size_t)which * BDIM * CN;
    unsigned char* s = spk + (size_t)which * BDIM * CN;

    float4 mem = make_float4(0.f, 0.f, 0.f, 0.f);
    #pragma unroll
    for (int t = 0; t < TT; ++t) {
        size_t off = (size_t)(t * BP + bp) * CN + (size_t)j4 * 4;
        float4 xi = *(const float4*)(p + off);
        mem.x = mem.x * 0.5f + xi.x;
        mem.y = mem.y * 0.5f + xi.y;
        mem.z = mem.z * 0.5f + xi.z;
        mem.w = mem.w * 0.5f + xi.w;
        uchar4 sp;
        sp.x = mem.x > 1.0f; if (sp.x) mem.x = 0.f;
        sp.y = mem.y > 1.0f; if (sp.y) mem.y = 0.f;
        sp.z = mem.z > 1.0f; if (sp.z) mem.z = 0.f;
        sp.w = mem.w > 1.0f; if (sp.w) mem.w = 0.f;
        *(uchar4*)(s + off) = sp;
    }
}

// ---------------------------------------------------------------------------
// Spiking attention via linear-attention reordering:
//   M[e][d]  = sum_m k[e][m] * v[d][m]          (popcount on bitpacked spikes)
//   out[d][n] = SCALE * sum_e q[e][n] * M[e][d]
// One CTA per (b, h). Exact integer arithmetic -> bit-identical to reference.
// ---------------------------------------------------------------------------
__global__ void __launch_bounds__(256)
attn_kernel(const unsigned char* __restrict__ spk,
            float* __restrict__ attn)
{
    const int bh = blockIdx.x;           // 0..511
    const int b  = bh / HH;
    const int h  = bh % HH;
    const size_t head_off = ((size_t)b * CDIM + (size_t)h * GDIM) * NDIM;
    const unsigned char* qS = spk + 0ull * BDIM * CN + head_off;
    const unsigned char* kS = spk + 1ull * BDIM * CN + head_off;
    const unsigned char* vS = spk + 2ull * BDIM * CN + head_off;

    __shared__ unsigned int kb[64][16];
    __shared__ unsigned int vb[64][16];
    __shared__ float        Ms[64][64];
    __shared__ unsigned char qs[64][128];

    const int tid  = threadIdx.x;
    const int lane = tid & 31;
    const int warp = tid >> 5;           // 8 warps

    // bitpack k and v rows via ballot
    #pragma unroll
    for (int r = 0; r < 8; ++r) {
        int e = warp * 8 + r;
        #pragma unroll
        for (int w = 0; w < 16; ++w) {
            unsigned int bkk = __ballot_sync(0xffffffffu, kS[(size_t)e * NDIM + w * 32 + lane] != 0);
            unsigned int bvv = __ballot_sync(0xffffffffu, vS[(size_t)e * NDIM + w * 32 + lane] != 0);
            if (lane == 0) { kb[e][w] = bkk; vb[e][w] = bvv; }
        }
    }
    __syncthreads();

    // M[e][d] * SCALE via popcount; 16 entries per thread
    {
        int e  = tid >> 2;
        int d0 = (tid & 3) * 16;
        unsigned int kr[16];
        #pragma unroll
        for (int w = 0; w < 16; ++w) kr[w] = kb[e][w];
        #pragma unroll
        for (int dd = 0; dd < 16; ++dd) {
            int d = d0 + dd;
            int s = 0;
            #pragma unroll
            for (int w = 0; w < 16; ++w) s += __popc(kr[w] & vb[d][w]);
            Ms[e][d] = (float)s * 0.125f;
        }
    }
    __syncthreads();

    // out[d][n] = sum_e q[e][n] * Ms[e][d]
    const int nLocal = tid & 127;         // n within chunk
    const int d0     = (tid >> 7) * 32;   // 0 or 32
    float* outp = attn + head_off;

    for (int ch = 0; ch < 4; ++ch) {
        const int nb = ch * 128;
        // stage q chunk (64 rows x 128 cols, u8)
        for (int w = tid; w < 2048; w += 256) {
            int e = w >> 5, nl4 = (w & 31) << 2;
            *(unsigned int*)&qs[e][nl4] =
                *(const unsigned int*)(qS + (size_t)e * NDIM + nb + nl4);
        }
        __syncthreads();

        float acc[32];
        #pragma unroll
        for (int j = 0; j < 32; ++j) acc[j] = 0.f;

        #pragma unroll 4
        for (int e = 0; e < 64; ++e) {
            float qv = (float)qs[e][nLocal];
            #pragma unroll
            for (int j = 0; j < 32; ++j)
                acc[j] += qv * Ms[e][d0 + j];
        }
        #pragma unroll
        for (int j = 0; j < 32; ++j)
            outp[(size_t)(d0 + j) * NDIM + nb + nLocal] = acc[j];
        __syncthreads();
    }
}

// ---------------------------------------------------------------------------
// launch
// ---------------------------------------------------------------------------
extern "C" void kernel_launch(void* const* d_in, const int* in_sizes, int n_in,
                              void* d_out, int out_size)
{
    (void)in_sizes; (void)n_in; (void)out_size;
    const float* x  = (const float*)d_in[0];
    const float* wq = (const float*)d_in[1];
    const float* wk = (const float*)d_in[2];
    const float* wv = (const float*)d_in[3];
    const float* wp = (const float*)d_in[4];
    const float* bg = (const float*)d_in[5];
    const float* bb = (const float*)d_in[6];
    const float* bm = (const float*)d_in[7];
    const float* bv = (const float*)d_in[8];
    float* out = (float*)d_out;

    float* pre;  unsigned char* spk;
    float* attn; unsigned char* spk4;
    cudaGetSymbolAddress((void**)&pre,  g_pre);
    cudaGetSymbolAddress((void**)&spk,  g_spk);
    cudaGetSymbolAddress((void**)&attn, g_attn);
    cudaGetSymbolAddress((void**)&spk4, g_spk4);

    dim3 blk(256);
    dim3 grd(NDIM / 128, CDIM / 128, BDIM);

    const float* W[3] = { wq, wk, wv };
    for (int w = 0; w < 3; ++w) {
        gemm_bn_kernel<float><<<grd, blk>>>(
            W[w], x, pre + (size_t)w * BDIM * CN,
            bg + w * CDIM, bb + w * CDIM, bm + w * CDIM, bv + w * CDIM);
    }

    {   // LIF over q/k/v pre-activations
        size_t total = 3ull * BP * (CN / 4);
        int blocks = (int)((total + 255) / 256);
        lif_kernel<<<blocks, 256>>>(pre, spk, 3);
    }

    attn_kernel<<<BDIM * HH, 256>>>(spk, attn);

    {   // LIF over attention output
        size_t total = 1ull * BP * (CN / 4);
        int blocks = (int)((total + 255) / 256);
        lif_kernel<<<blocks, 256>>>(attn, spk4, 1);
    }

    gemm_bn_kernel<unsigned char><<<grd, blk>>>(
        wp, spk4, out,
        bg + 3 * CDIM, bb + 3 * CDIM, bm + 3 * CDIM, bv + 3 * CDIM);
}

// round 3
// speedup vs baseline: 1.1325x; 1.1055x over previous
#include <cuda_runtime.h>
#include <cstdint>
#include <cmath>

#define CDIM 512
#define NDIM 512
#define BDIM 64
#define TT 4
#define BP 16           // BDIM / TT
#define HH 8
#define GDIM 64
#define EPSF 1e-5f
#define CN (CDIM*NDIM)  // 262144

// ---------------------------------------------------------------------------
// Scratch (device globals: allocation-free per harness rules)
// ---------------------------------------------------------------------------
__device__ float         g_pre [3ull*BDIM*CN];   // qkv pre-activations
__device__ unsigned char g_spk [3ull*BDIM*CN];   // qkv spikes
__device__ float         g_attn[(unsigned long long)BDIM*CN]; // attn out pre-LIF
__device__ unsigned char g_spk4[(unsigned long long)BDIM*CN]; // final spikes

// ---------------------------------------------------------------------------
// helpers
// ---------------------------------------------------------------------------
__device__ __forceinline__ float4 load4(const float* p) { return *(const float4*)p; }
__device__ __forceinline__ float4 load4(const unsigned char* p) {
    uchar4 u = *(const uchar4*)p;
    return make_float4((float)u.x, (float)u.y, (float)u.z, (float)u.w);
}

// packed fp32x2 FMA (SASS FFMA2): d = a*b + d, two lanes per issue.
// Bit-identical fp32 arithmetic; ptxas never emits this from C++.
__device__ __forceinline__ void ffma2(unsigned long long& d,
                                      unsigned long long a,
                                      unsigned long long b) {
    asm("fma.rn.f32x2 %0, %1, %2, %0;" : "+l"(d) : "l"(a), "l"(b));
}
__device__ __forceinline__ unsigned long long pack2(float x, float y) {
    unsigned long long r;
    asm("mov.b64 %0, {%1, %2};" : "=l"(r) : "f"(x), "f"(y));
    return r;
}
__device__ __forceinline__ float2 unpack2(unsigned long long v) {
    float2 r;
    asm("mov.b64 {%0, %1}, %2;" : "=f"(r.x), "=f"(r.y) : "l"(v));
    return r;
}

// ---------------------------------------------------------------------------
// Fused 1x1-conv (GEMM) + BatchNorm epilogue.
// Y[b][o][n] = inv[o] * sum_c A[o][c] * X[b][c][n] + bias[o]
// CTA 128x128, K-tile 16, 256 threads, 8x8 per thread, double buffer.
// Inner product uses packed fma.rn.f32x2 (FFMA2): 32 issues instead of 64.
// ---------------------------------------------------------------------------
template<typename TIn>
__global__ void __launch_bounds__(256, 2)
gemm_bn_kernel(const float* __restrict__ A,
               const TIn*  __restrict__ Xbase,
               float*      __restrict__ Ybase,
               const float* __restrict__ bn_g,
               const float* __restrict__ bn_b,
               const float* __restrict__ bn_m,
               const float* __restrict__ bn_v)
{
    const int b = blockIdx.z;
    const TIn*  X = Xbase + (size_t)b * CN;
    float*      Y = Ybase + (size_t)b * CN;

    __shared__ float As[2][16][128];
    __shared__ float Xs[2][16][128];

    const int tid   = threadIdx.x;
    const int mBase = blockIdx.y * 128;
    const int nBase = blockIdx.x * 128;
    const int row0  = (tid >> 4) * 8;   // 0..120
    const int col0  = (tid & 15) * 8;   // 0..120

    // accumulators: pairs along j (8 rows x 4 f32x2-pairs = 64 fp32)
    unsigned long long acc[8][4];
    const unsigned long long z2 = pack2(0.f, 0.f);
    #pragma unroll
    for (int i = 0; i < 8; ++i)
        #pragma unroll
        for (int j = 0; j < 4; ++j) acc[i][j] = z2;

    // prologue: load k-tile 0
    #pragma unroll
    for (int i = 0; i < 2; ++i) {
        int f4 = tid + i * 256;
        int r  = f4 >> 2, kc = (f4 & 3) * 4;
        float4 va = load4(A + (size_t)(mBase + r) * CDIM + kc);
        As[0][kc+0][r] = va.x; As[0][kc+1][r] = va.y;
        As[0][kc+2][r] = va.z; As[0][kc+3][r] = va.w;
        int kr = f4 >> 5, nc = (f4 & 31) * 4;
        float4 vx = load4(X + (size_t)kr * NDIM + nBase + nc);
        *(float4*)&Xs[0][kr][nc] = vx;
    }
    __syncthreads();

    int buf = 0;
    for (int kt = 0; kt < 32; ++kt) {
        float4 pa[2], px[2];
        if (kt < 31) {
            const int k0 = (kt + 1) * 16;
            #pragma unroll
            for (int i = 0; i < 2; ++i) {
                int f4 = tid + i * 256;
                int r  = f4 >> 2, kc = (f4 & 3) * 4;
                pa[i] = load4(A + (size_t)(mBase + r) * CDIM + k0 + kc);
                int kr = f4 >> 5, nc = (f4 & 31) * 4;
                px[i] = load4(X + (size_t)(k0 + kr) * NDIM + nBase + nc);
            }
        }
        #pragma unroll
        for (int kk = 0; kk < 16; ++kk) {
            float a[8];
            *(float4*)&a[0]  = *(float4*)&As[buf][kk][row0];
            *(float4*)&a[4]  = *(float4*)&As[buf][kk][row0 + 4];
            // Xs pairs read directly as b64 lanes (float2 layout == b64)
            ulonglong2 b01 = *(const ulonglong2*)&Xs[buf][kk][col0];
            ulonglong2 b23 = *(const ulonglong2*)&Xs[buf][kk][col0 + 4];
            unsigned long long bp[4] = { b01.x, b01.y, b23.x, b23.y };
            #pragma unroll
            for (int i = 0; i < 8; ++i) {
                unsigned long long aa = pack2(a[i], a[i]);
                #pragma unroll
                for (int j = 0; j < 4; ++j)
                    ffma2(acc[i][j], aa, bp[j]);
            }
        }
        if (kt < 31) {
            #pragma unroll
            for (int i = 0; i < 2; ++i) {
                int f4 = tid + i * 256;
                int r  = f4 >> 2, kc = (f4 & 3) * 4;
                As[buf^1][kc+0][r] = pa[i].x; As[buf^1][kc+1][r] = pa[i].y;
                As[buf^1][kc+2][r] = pa[i].z; As[buf^1][kc+3][r] = pa[i].w;
                int kr = f4 >> 5, nc = (f4 & 31) * 4;
                *(float4*)&Xs[buf^1][kr][nc] = px[i];
            }
        }
        __syncthreads();
        buf ^= 1;
    }

    // epilogue: BN (eval mode): y*inv + (beta - mean*inv)
    #pragma unroll
    for (int i = 0; i < 8; ++i) {
        int o = mBase + row0 + i;
        float inv  = bn_g[o] / sqrtf(bn_v[o] + EPSF);
        float bias = bn_b[o] - bn_m[o] * inv;
        float2 p0 = unpack2(acc[i][0]);
        float2 p1 = unpack2(acc[i][1]);
        float2 p2 = unpack2(acc[i][2]);
        float2 p3 = unpack2(acc[i][3]);
        float4 r0, r1;
        r0.x = p0.x*inv + bias; r0.y = p0.y*inv + bias;
        r0.z = p1.x*inv + bias; r0.w = p1.y*inv + bias;
        r1.x = p2.x*inv + bias; r1.y = p2.y*inv + bias;
        r1.z = p3.x*inv + bias; r1.w = p3.y*inv + bias;
        *(float4*)(Y + (size_t)o * NDIM + nBase + col0)     = r0;
        *(float4*)(Y + (size_t)o * NDIM + nBase + col0 + 4) = r1;
    }
}

// ---------------------------------------------------------------------------
// LIF scan over T timesteps. Batch index b = t*BP + b'.
// mem = mem*0.5 + x ; spike = mem > 1 ; mem = spike ? 0 : mem
// ---------------------------------------------------------------------------
__global__ void lif_kernel(const float* __restrict__ pre,
                           unsigned char* __restrict__ spk,
                           int ntensors)
{
    size_t idx   = (size_t)blockIdx.x * blockDim.x + threadIdx.x;
    size_t total = (size_t)ntensors * BP * (CN / 4);
    if (idx >= total) return;
    int j4    = (int)(idx % (CN / 4));
    int rest  = (int)(idx / (CN / 4));
    int bp    = rest % BP;
    int which = rest / BP;

    const float* p = pre + (size_t)which * BDIM * CN;
    unsigned char* s = spk + (size_t)which * BDIM * CN;

    float4 mem = make_float4(0.f, 0.f, 0.f, 0.f);
    #pragma unroll
    for (int t = 0; t < TT; ++t) {
        size_t off = (size_t)(t * BP + bp) * CN + (size_t)j4 * 4;
        float4 xi = *(const float4*)(p + off);
        mem.x = mem.x * 0.5f + xi.x;
        mem.y = mem.y * 0.5f + xi.y;
        mem.z = mem.z * 0.5f + xi.z;
        mem.w = mem.w * 0.5f + xi.w;
        uchar4 sp;
        sp.x = mem.x > 1.0f; if (sp.x) mem.x = 0.f;
        sp.y = mem.y > 1.0f; if (sp.y) mem.y = 0.f;
        sp.z = mem.z > 1.0f; if (sp.z) mem.z = 0.f;
        sp.w = mem.w > 1.0f; if (sp.w) mem.w = 0.f;
        *(uchar4*)(s + off) = sp;
    }
}

// ---------------------------------------------------------------------------
// Spiking attention via linear-attention reordering:
//   M[e][d]  = sum_m k[e][m] * v[d][m]          (popcount on bitpacked spikes)
//   out[d][n] = SCALE * sum_e q[e][n] * M[e][d]
// One CTA per (b, h). Exact integer arithmetic -> bit-identical to reference.
// ---------------------------------------------------------------------------
__global__ void __launch_bounds__(256)
attn_kernel(const unsigned char* __restrict__ spk,
            float* __restrict__ attn)
{
    const int bh = blockIdx.x;           // 0..511
    const int b  = bh / HH;
    const int h  = bh % HH;
    const size_t head_off = ((size_t)b * CDIM + (size_t)h * GDIM) * NDIM;
    const unsigned char* qS = spk + 0ull * BDIM * CN + head_off;
    const unsigned char* kS = spk + 1ull * BDIM * CN + head_off;
    const unsigned char* vS = spk + 2ull * BDIM * CN + head_off;

    __shared__ unsigned int kb[64][16];
    __shared__ unsigned int vb[64][16];
    __shared__ float        Ms[64][64];
    __shared__ unsigned char qs[64][128];

    const int tid  = threadIdx.x;
    const int lane = tid & 31;
    const int warp = tid >> 5;           // 8 warps

    // bitpack k and v rows via ballot
    #pragma unroll
    for (int r = 0; r < 8; ++r) {
        int e = warp * 8 + r;
        #pragma unroll
        for (int w = 0; w < 16; ++w) {
            unsigned int bkk = __ballot_sync(0xffffffffu, kS[(size_t)e * NDIM + w * 32 + lane] != 0);
            unsigned int bvv = __ballot_sync(0xffffffffu, vS[(size_t)e * NDIM + w * 32 + lane] != 0);
            if (lane == 0) { kb[e][w] = bkk; vb[e][w] = bvv; }
        }
    }
    __syncthreads();

    // M[e][d] * SCALE via popcount; 16 entries per thread
    {
        int e  = tid >> 2;
        int d0 = (tid & 3) * 16;
        unsigned int kr[16];
        #pragma unroll
        for (int w = 0; w < 16; ++w) kr[w] = kb[e][w];
        #pragma unroll
        for (int dd = 0; dd < 16; ++dd) {
            int d = d0 + dd;
            int s = 0;
            #pragma unroll
            for (int w = 0; w < 16; ++w) s += __popc(kr[w] & vb[d][w]);
            Ms[e][d] = (float)s * 0.125f;
        }
    }
    __syncthreads();

    // out[d][n] = sum_e q[e][n] * Ms[e][d]
    const int nLocal = tid & 127;         // n within chunk
    const int d0     = (tid >> 7) * 32;   // 0 or 32
    float* outp = attn + head_off;

    for (int ch = 0; ch < 4; ++ch) {
        const int nb = ch * 128;
        // stage q chunk (64 rows x 128 cols, u8)
        for (int w = tid; w < 2048; w += 256) {
            int e = w >> 5, nl4 = (w & 31) << 2;
            *(unsigned int*)&qs[e][nl4] =
                *(const unsigned int*)(qS + (size_t)e * NDIM + nb + nl4);
        }
        __syncthreads();

        float acc[32];
        #pragma unroll
        for (int j = 0; j < 32; ++j) acc[j] = 0.f;

        #pragma unroll 4
        for (int e = 0; e < 64; ++e) {
            float qv = (float)qs[e][nLocal];
            #pragma unroll
            for (int j = 0; j < 32; ++j)
                acc[j] += qv * Ms[e][d0 + j];
        }
        #pragma unroll
        for (int j = 0; j < 32; ++j)
            outp[(size_t)(d0 + j) * NDIM + nb + nLocal] = acc[j];
        __syncthreads();
    }
}

// ---------------------------------------------------------------------------
// launch
// ---------------------------------------------------------------------------
extern "C" void kernel_launch(void* const* d_in, const int* in_sizes, int n_in,
                              void* d_out, int out_size)
{
    (void)in_sizes; (void)n_in; (void)out_size;
    const float* x  = (const float*)d_in[0];
    const float* wq = (const float*)d_in[1];
    const float* wk = (const float*)d_in[2];
    const float* wv = (const float*)d_in[3];
    const float* wp = (const float*)d_in[4];
    const float* bg = (const float*)d_in[5];
    const float* bb = (const float*)d_in[6];
    const float* bm = (const float*)d_in[7];
    const float* bv = (const float*)d_in[8];
    float* out = (float*)d_out;

    float* pre;  unsigned char* spk;
    float* attn; unsigned char* spk4;
    cudaGetSymbolAddress((void**)&pre,  g_pre);
    cudaGetSymbolAddress((void**)&spk,  g_spk);
    cudaGetSymbolAddress((void**)&attn, g_attn);
    cudaGetSymbolAddress((void**)&spk4, g_spk4);

    dim3 blk(256);
    dim3 grd(NDIM / 128, CDIM / 128, BDIM);

    const float* W[3] = { wq, wk, wv };
    for (int w = 0; w < 3; ++w) {
        gemm_bn_kernel<float><<<grd, blk>>>(
            W[w], x, pre + (size_t)w * BDIM * CN,
            bg + w * CDIM, bb + w * CDIM, bm + w * CDIM, bv + w * CDIM);
    }

    {   // LIF over q/k/v pre-activations
        size_t total = 3ull * BP * (CN / 4);
        int blocks = (int)((total + 255) / 256);
        lif_kernel<<<blocks, 256>>>(pre, spk, 3);
    }

    attn_kernel<<<BDIM * HH, 256>>>(spk, attn);

    {   // LIF over attention output
        size_t total = 1ull * BP * (CN / 4);
        int blocks = (int)((total + 255) / 256);
        lif_kernel<<<blocks, 256>>>(attn, spk4, 1);
    }

    gemm_bn_kernel<unsigned char><<<grd, blk>>>(
        wp, spk4, out,
        bg + 3 * CDIM, bb + 3 * CDIM, bm + 3 * CDIM, bv + 3 * CDIM);
}

// round 5
// speedup vs baseline: 2.6343x; 2.3261x over previous
#include <cuda_runtime.h>
#include <cuda_fp16.h>
#include <cstdint>
#include <cmath>

#define CDIM 512
#define NDIM 512
#define BDIM 64
#define TT 4
#define BP 16           // BDIM / TT
#define HH 8
#define GDIM 64
#define EPSF 1e-5f
#define CN (CDIM*NDIM)  // 262144
#define MTOT_QKV 1536

// ---------------------------------------------------------------------------
// Scratch (device globals: allocation-free per harness rules)
// ---------------------------------------------------------------------------
__device__ __half        g_w2  [2ull*MTOT_QKV*CDIM];          // qkv weight splits
__device__ __half        g_wp2 [2ull*CDIM*CDIM];              // proj weight splits
__device__ __half        g_xt2 [2ull*BDIM*CN];                // x splits, [s][b][n][c]
__device__ float         g_pre [3ull*BDIM*CN];                // qkv pre-acts [w][b][c][n]
__device__ unsigned char g_spk [3ull*BDIM*CN];                // qkv spikes
__device__ float         g_attn[(unsigned long long)BDIM*CN];
__device__ unsigned char g_spk4[(unsigned long long)BDIM*CN];
__device__ __half        g_st  [(unsigned long long)BDIM*CN]; // spk4 fp16 [b][n][c]

// ---------------------------------------------------------------------------
// PTX helpers (all baseline sm_80+: valid on compute_103 target)
// ---------------------------------------------------------------------------
__device__ __forceinline__ uint32_t smem_u32(const void* p) {
    uint32_t a;
    asm("{ .reg .u64 t; cvta.to.shared.u64 t, %1; cvt.u32.u64 %0, t; }" : "=r"(a) : "l"(p));
    return a;
}
#define LDSM4(r0,r1,r2,r3,addr) \
    asm volatile("ldmatrix.sync.aligned.m8n8.x4.shared.b16 {%0,%1,%2,%3}, [%4];" \
        : "=r"(r0),"=r"(r1),"=r"(r2),"=r"(r3) : "r"(addr))

__device__ __forceinline__ void mma16816(float* c, const uint32_t* a,
                                         uint32_t b0, uint32_t b1) {
    asm volatile("mma.sync.aligned.m16n8k16.row.col.f32.f16.f16.f32 "
        "{%0,%1,%2,%3}, {%4,%5,%6,%7}, {%8,%9}, {%0,%1,%2,%3};"
        : "+f"(c[0]), "+f"(c[1]), "+f"(c[2]), "+f"(c[3])
        : "r"(a[0]), "r"(a[1]), "r"(a[2]), "r"(a[3]), "r"(b0), "r"(b1));
}
__device__ __forceinline__ void cp_async16(uint32_t dst, const void* src) {
    asm volatile("cp.async.cg.shared.global [%0], [%1], 16;" :: "r"(dst), "l"(src));
}
__device__ __forceinline__ uint32_t swz(uint32_t bo) {
    return bo ^ (((bo >> 7) & 7u) << 4);
}

// ---------------------------------------------------------------------------
// Weight splits: w -> (fp16 hi, fp16 residual)
// ---------------------------------------------------------------------------
__global__ void wsplit_kernel(const float* __restrict__ wq, const float* __restrict__ wk,
                              const float* __restrict__ wv, const float* __restrict__ wp)
{
    int i = blockIdx.x * 256 + threadIdx.x;
    if (i < MTOT_QKV * CDIM) {
        int o = i >> 9;
        const float* src = (o < 512) ? wq : (o < 1024 ? wk : wv);
        float v = src[((o & 511) << 9) | (i & 511)];
        __half h0 = __float2half_rn(v);
        float r1 = v - __half2float(h0);
        g_w2[i] = h0;
        g_w2[(size_t)MTOT_QKV * CDIM + i] = __float2half_rn(r1);
    }
    if (i < CDIM * CDIM) {
        float v = wp[i];
        __half h0 = __float2half_rn(v);
        float r1 = v - __half2float(h0);
        g_wp2[i] = h0;
        g_wp2[(size_t)CDIM * CDIM + i] = __float2half_rn(r1);
    }
}

// ---------------------------------------------------------------------------
// x split + transpose: x[b][c][n] fp32 -> g_xt2[s][b][n][c] fp16 (2 splits)
// ---------------------------------------------------------------------------
__global__ void xsplit_kernel(const float* __restrict__ x)
{
    __shared__ float tile[32][33];
    const int b = blockIdx.z, c0 = blockIdx.y * 32, n0 = blockIdx.x * 32;
    const float* xb = x + (size_t)b * CN;
    const int tx = threadIdx.x, ty = threadIdx.y;   // 32 x 8
    #pragma unroll
    for (int r = 0; r < 4; ++r) {
        int cl = ty * 4 + r;
        tile[cl][tx] = xb[(size_t)(c0 + cl) * NDIM + n0 + tx];
    }
    __syncthreads();
    const size_t SEG = (size_t)BDIM * CN;
    #pragma unroll
    for (int r = 0; r < 4; ++r) {
        int nl = ty * 4 + r, cl = tx;
        float v = tile[cl][nl];
        __half h0 = __float2half_rn(v);
        float r1 = v - __half2float(h0);
        size_t o = ((size_t)b * NDIM + (n0 + nl)) * CDIM + c0 + cl;
        g_xt2[o] = h0;
        g_xt2[SEG + o] = __float2half_rn(r1);
    }
}

// spk4 u8 [b][c][n] -> fp16 transposed [b][n][c] (spikes exact in fp16)
__global__ void spkt_kernel()
{
    __shared__ unsigned char tile[32][33];
    const int b = blockIdx.z, c0 = blockIdx.y * 32, n0 = blockIdx.x * 32;
    const unsigned char* sb = g_spk4 + (size_t)b * CN;
    const int tx = threadIdx.x, ty = threadIdx.y;
    #pragma unroll
    for (int r = 0; r < 4; ++r) {
        int cl = ty * 4 + r;
        tile[cl][tx] = sb[(size_t)(c0 + cl) * NDIM + n0 + tx];
    }
    __syncthreads();
    #pragma unroll
    for (int r = 0; r < 4; ++r) {
        int nl = ty * 4 + r, cl = tx;
        g_st[((size_t)b * NDIM + (n0 + nl)) * CDIM + c0 + cl] =
            __float2half_rn((float)tile[cl][nl]);
    }
}

// ---------------------------------------------------------------------------
// HMMA split-GEMM + BN.  One CTA: 128(M) x 128(N), K stacked over split
// product segments (each K=512, chunked by 64).  8 warps, 64x32 per warp.
// ---------------------------------------------------------------------------
struct PArg {
    const __half* A[3];   // per-product A base (weight split), row-major [M][512]
    const __half* Bb[3];  // per-product B base (x split), [b][n][c] (add b*CN in kernel)
    int np;
};

__device__ __forceinline__ void load_chunk(
    const __half* __restrict__ Aseg, const __half* __restrict__ Bseg,
    int mBase, int n0g, int kOff, uint32_t smemBuf, int tid)
{
    #pragma unroll
    for (int it = 0; it < 8; ++it) {
        int i = tid + it * 256;          // 0..2047
        int r = (i >> 3) & 127;
        int s = i & 7;
        bool isA = i < 1024;
        const __half* g = isA ? (Aseg + (size_t)(mBase + r) * CDIM + kOff + s * 8)
                              : (Bseg + (size_t)(n0g + r) * CDIM + kOff + s * 8);
        uint32_t bo = (uint32_t)(r * 128 + s * 16);
        cp_async16(smemBuf + (isA ? 0u : 16384u) + swz(bo), g);
    }
}

__global__ void __launch_bounds__(256, 2)
gemm_hmma(PArg pa, float* __restrict__ Ybase,
          const float* __restrict__ bg, const float* __restrict__ bb,
          const float* __restrict__ bm, const float* __restrict__ bv,
          int isProj)
{
    extern __shared__ __align__(128) unsigned char dsm[];
    const uint32_t sbase = smem_u32(dsm);
    const int tid = threadIdx.x, lane = tid & 31, wid = tid >> 5;
    const int warpM = wid >> 2, warpN = wid & 3;       // 2 x 4 warp grid
    const int b = blockIdx.z;
    const int mBase = blockIdx.y * 128;
    const int n0g   = blockIdx.x * 128;

    float acc[4][4][4];
    #pragma unroll
    for (int i = 0; i < 4; ++i)
        #pragma unroll
        for (int j = 0; j < 4; ++j)
            #pragma unroll
            for (int k = 0; k < 4; ++k) acc[i][j][k] = 0.f;

    const int nch = pa.np * 8;

    load_chunk(pa.A[0], pa.Bb[0] + (size_t)b * CN, mBase, n0g, 0, sbase, tid);
    asm volatile("cp.async.commit_group;");

    int buf = 0;
    for (int c = 0; c < nch; ++c) {
        if (c + 1 < nch) {
            int p = (c + 1) >> 3, ko = ((c + 1) & 7) * 64;
            load_chunk(pa.A[p], pa.Bb[p] + (size_t)b * CN, mBase, n0g, ko,
                       sbase + (buf ^ 1) * 32768, tid);
            asm volatile("cp.async.commit_group;");
            asm volatile("cp.async.wait_group 1;");
        } else {
            asm volatile("cp.async.wait_group 0;");
        }
        __syncthreads();

        const uint32_t aB = sbase + buf * 32768;
        const uint32_t bB = aB + 16384;
        #pragma unroll
        for (int ks = 0; ks < 4; ++ks) {
            uint32_t ra[4][4], rb[2][4];
            #pragma unroll
            for (int mt = 0; mt < 4; ++mt) {
                int row = warpM * 64 + mt * 16 + (lane & 7) + ((lane >> 3) & 1) * 8;
                int kh  = ks * 16 + (lane >> 4) * 8;
                uint32_t bo = (uint32_t)(row * 128 + kh * 2);
                LDSM4(ra[mt][0], ra[mt][1], ra[mt][2], ra[mt][3], aB + swz(bo));
            }
            #pragma unroll
            for (int nt2 = 0; nt2 < 2; ++nt2) {
                int nrow = warpN * 32 + nt2 * 16 + (lane & 7) + ((lane >> 4) & 1) * 8;
                int kh   = ks * 16 + ((lane >> 3) & 1) * 8;
                uint32_t bo = (uint32_t)(nrow * 128 + kh * 2);
                LDSM4(rb[nt2][0], rb[nt2][1], rb[nt2][2], rb[nt2][3], bB + swz(bo));
            }
            #pragma unroll
            for (int mt = 0; mt < 4; ++mt)
                #pragma unroll
                for (int nt = 0; nt < 4; ++nt)
                    mma16816(acc[mt][nt], ra[mt],
                             rb[nt >> 1][(nt & 1) * 2], rb[nt >> 1][(nt & 1) * 2 + 1]);
        }
        __syncthreads();
        buf ^= 1;
    }

    // epilogue: BN + store
    #pragma unroll
    for (int mt = 0; mt < 4; ++mt) {
        int o0 = mBase + warpM * 64 + mt * 16 + (lane >> 2);
        #pragma unroll
        for (int hf = 0; hf < 2; ++hf) {
            int o = o0 + hf * 8;
            int bnIdx; float* rowP;
            if (isProj) {
                bnIdx = 3 * CDIM + o;
                rowP  = Ybase + ((size_t)b * CDIM + o) * NDIM;
            } else {
                int w = o >> 9, cc = o & 511;
                bnIdx = w * CDIM + cc;
                rowP  = Ybase + (((size_t)w * BDIM + b) * CDIM + cc) * NDIM;
            }
            float inv  = bg[bnIdx] / sqrtf(bv[bnIdx] + EPSF);
            float bias = bb[bnIdx] - bm[bnIdx] * inv;
            #pragma unroll
            for (int nt = 0; nt < 4; ++nt) {
                int nn = n0g + warpN * 32 + nt * 8 + (lane & 3) * 2;
                float2 v;
                v.x = acc[mt][nt][hf * 2 + 0] * inv + bias;
                v.y = acc[mt][nt][hf * 2 + 1] * inv + bias;
                *(float2*)(rowP + nn) = v;
            }
        }
    }
}

// ---------------------------------------------------------------------------
// LIF scan (DRAM-roofline-bound, unchanged)
// ---------------------------------------------------------------------------
__global__ void lif_kernel(const float* __restrict__ pre,
                           unsigned char* __restrict__ spk,
                           int ntensors)
{
    size_t idx   = (size_t)blockIdx.x * blockDim.x + threadIdx.x;
    size_t total = (size_t)ntensors * BP * (CN / 4);
    if (idx >= total) return;
    int j4    = (int)(idx % (CN / 4));
    int rest  = (int)(idx / (CN / 4));
    int bp    = rest % BP;
    int which = rest / BP;

    const float* p = pre + (size_t)which * BDIM * CN;
    unsigned char* s = spk + (size_t)which * BDIM * CN;

    float4 mem = make_float4(0.f, 0.f, 0.f, 0.f);
    #pragma unroll
    for (int t = 0; t < TT; ++t) {
        size_t off = (size_t)(t * BP + bp) * CN + (size_t)j4 * 4;
        float4 xi = *(const float4*)(p + off);
        mem.x = mem.x * 0.5f + xi.x;
        mem.y = mem.y * 0.5f + xi.y;
        mem.z = mem.z * 0.5f + xi.z;
        mem.w = mem.w * 0.5f + xi.w;
        uchar4 sp;
        sp.x = mem.x > 1.0f; if (sp.x) mem.x = 0.f;
        sp.y = mem.y > 1.0f; if (sp.y) mem.y = 0.f;
        sp.z = mem.z > 1.0f; if (sp.z) mem.z = 0.f;
        sp.w = mem.w > 1.0f; if (sp.w) mem.w = 0.f;
        *(uchar4*)(s + off) = sp;
    }
}

// ---------------------------------------------------------------------------
// Spiking attention (bit-exact popcount reordering, unchanged)
// ---------------------------------------------------------------------------
__global__ void __launch_bounds__(256)
attn_kernel(const unsigned char* __restrict__ spk,
            float* __restrict__ attn)
{
    const int bh = blockIdx.x;
    const int b  = bh / HH;
    const int h  = bh % HH;
    const size_t head_off = ((size_t)b * CDIM + (size_t)h * GDIM) * NDIM;
    const unsigned char* qS = spk + 0ull * BDIM * CN + head_off;
    const unsigned char* kS = spk + 1ull * BDIM * CN + head_off;
    const unsigned char* vS = spk + 2ull * BDIM * CN + head_off;

    __shared__ unsigned int kb[64][16];
    __shared__ unsigned int vb[64][16];
    __shared__ float        Ms[64][64];
    __shared__ unsigned char qs[64][128];

    const int tid  = threadIdx.x;
    const int lane = tid & 31;
    const int warp = tid >> 5;

    #pragma unroll
    for (int r = 0; r < 8; ++r) {
        int e = warp * 8 + r;
        #pragma unroll
        for (int w = 0; w < 16; ++w) {
            unsigned int bkk = __ballot_sync(0xffffffffu, kS[(size_t)e * NDIM + w * 32 + lane] != 0);
            unsigned int bvv = __ballot_sync(0xffffffffu, vS[(size_t)e * NDIM + w * 32 + lane] != 0);
            if (lane == 0) { kb[e][w] = bkk; vb[e][w] = bvv; }
        }
    }
    __syncthreads();

    {
        int e  = tid >> 2;
        int d0 = (tid & 3) * 16;
        unsigned int kr[16];
        #pragma unroll
        for (int w = 0; w < 16; ++w) kr[w] = kb[e][w];
        #pragma unroll
        for (int dd = 0; dd < 16; ++dd) {
            int d = d0 + dd;
            int s = 0;
            #pragma unroll
            for (int w = 0; w < 16; ++w) s += __popc(kr[w] & vb[d][w]);
            Ms[e][d] = (float)s * 0.125f;
        }
    }
    __syncthreads();

    const int nLocal = tid & 127;
    const int d0     = (tid >> 7) * 32;
    float* outp = attn + head_off;

    for (int ch = 0; ch < 4; ++ch) {
        const int nb = ch * 128;
        for (int w = tid; w < 2048; w += 256) {
            int e = w >> 5, nl4 = (w & 31) << 2;
            *(unsigned int*)&qs[e][nl4] =
                *(const unsigned int*)(qS + (size_t)e * NDIM + nb + nl4);
        }
        __syncthreads();

        float acc[32];
        #pragma unroll
        for (int j = 0; j < 32; ++j) acc[j] = 0.f;

        #pragma unroll 4
        for (int e = 0; e < 64; ++e) {
            float qv = (float)qs[e][nLocal];
            #pragma unroll
            for (int j = 0; j < 32; ++j)
                acc[j] += qv * Ms[e][d0 + j];
        }
        #pragma unroll
        for (int j = 0; j < 32; ++j)
            outp[(size_t)(d0 + j) * NDIM + nb + nLocal] = acc[j];
        __syncthreads();
    }
}

// ---------------------------------------------------------------------------
// launch
// ---------------------------------------------------------------------------
extern "C" void kernel_launch(void* const* d_in, const int* in_sizes, int n_in,
                              void* d_out, int out_size)
{
    (void)in_sizes; (void)n_in; (void)out_size;
    const float* x  = (const float*)d_in[0];
    const float* wq = (const float*)d_in[1];
    const float* wk = (const float*)d_in[2];
    const float* wv = (const float*)d_in[3];
    const float* wv_ = (const float*)d_in[4];
    const float* bg = (const float*)d_in[5];
    const float* bb = (const float*)d_in[6];
    const float* bm = (const float*)d_in[7];
    const float* bv = (const float*)d_in[8];
    float* out = (float*)d_out;
    const float* wp = wv_;

    cudaFuncSetAttribute(gemm_hmma, cudaFuncAttributeMaxDynamicSharedMemorySize, 65536);

    float* pre;  unsigned char* spk;
    float* attn; unsigned char* spk4;
    __half *w2, *wp2, *xt2, *st;
    cudaGetSymbolAddress((void**)&pre,  g_pre);
    cudaGetSymbolAddress((void**)&spk,  g_spk);
    cudaGetSymbolAddress((void**)&attn, g_attn);
    cudaGetSymbolAddress((void**)&spk4, g_spk4);
    cudaGetSymbolAddress((void**)&w2,   g_w2);
    cudaGetSymbolAddress((void**)&wp2,  g_wp2);
    cudaGetSymbolAddress((void**)&xt2,  g_xt2);
    cudaGetSymbolAddress((void**)&st,   g_st);

    // 1. splits
    wsplit_kernel<<<(MTOT_QKV*CDIM + 255)/256, 256>>>(wq, wk, wv, wp);
    xsplit_kernel<<<dim3(16,16,BDIM), dim3(32,8)>>>(x);

    // 2. fused qkv GEMM+BN: products w0x0, w1x0 (B reuse), w0x1
    PArg pq;
    pq.np = 3;
    pq.A[0] = w2;                                pq.Bb[0] = xt2;
    pq.A[1] = w2 + (size_t)MTOT_QKV*CDIM;        pq.Bb[1] = xt2;
    pq.A[2] = w2;                                pq.Bb[2] = xt2 + (size_t)BDIM*CN;
    gemm_hmma<<<dim3(4, MTOT_QKV/128, BDIM), 256, 65536>>>(
        pq, pre, bg, bb, bm, bv, 0);

    // 3. LIF over q/k/v pre-activations
    {
        size_t total = 3ull * BP * (CN / 4);
        lif_kernel<<<(int)((total + 255)/256), 256>>>(pre, spk, 3);
    }

    // 4. spiking attention (exact popcount path)
    attn_kernel<<<BDIM * HH, 256>>>(spk, attn);

    // 5. LIF over attention output
    {
        size_t total = 1ull * BP * (CN / 4);
        lif_kernel<<<(int)((total + 255)/256), 256>>>(attn, spk4, 1);
    }

    // 6. spike transpose to fp16 [b][n][c]
    spkt_kernel<<<dim3(16,16,BDIM), dim3(32,8)>>>();

    // 7. proj GEMM+BN: products w0s, w1s (spikes exact in fp16)
    PArg pp;
    pp.np = 2;
    pp.A[0] = wp2;                               pp.Bb[0] = st;
    pp.A[1] = wp2 + (size_t)CDIM*CDIM;           pp.Bb[1] = st;
    gemm_hmma<<<dim3(4, CDIM/128, BDIM), 256, 65536>>>(
        pp, out, bg, bb, bm, bv, 1);
}